// round 1
// baseline (speedup 1.0000x reference)
#include <cuda_runtime.h>
#include <cuda_fp16.h>
#include <math.h>
#include <stdint.h>

#define NTOK 4096
#define DDIM 1024
#define HDIM 4096
#define NEXP 8
#define NGRP 9            // 8 experts + 1 shared expert
#define HROWS (3 * NTOK)  // 2*N expert rows (top-2) + N shared rows, compact

// ---------------------------------------------------------------------------
// Device-global scratch (allocation-free kernel_launch requirement)
// ---------------------------------------------------------------------------
__device__ __half g_xh  [(size_t)NTOK * DDIM];
__device__ __half g_w1h [(size_t)NEXP * DDIM * HDIM];
__device__ __half g_w2h [(size_t)NEXP * HDIM * DDIM];
__device__ __half g_sw1h[(size_t)DDIM * HDIM];
__device__ __half g_sw2h[(size_t)HDIM * DDIM];
__device__ __half g_h   [(size_t)HROWS * HDIM];
__device__ int    g_tok [NEXP * NTOK];
__device__ float  g_wt  [NEXP * NTOK];
__device__ int    g_cnt [NEXP];
__device__ int    g_base[NGRP];
__device__ float  g_imp [NEXP];
__device__ int    g_load[NEXP];

// ---------------------------------------------------------------------------
// Small helpers
// ---------------------------------------------------------------------------
__device__ __forceinline__ void cp_async16(uint32_t s, const void* g) {
    asm volatile("cp.async.cg.shared.global [%0], [%1], 16;\n" :: "r"(s), "l"(g));
}
__device__ __forceinline__ void cp_commit() {
    asm volatile("cp.async.commit_group;\n");
}
template <int NN>
__device__ __forceinline__ void cp_wait() {
    asm volatile("cp.async.wait_group %0;\n" :: "n"(NN));
}
__device__ __forceinline__ void ldsm4(uint32_t* r, uint32_t addr) {
    asm volatile("ldmatrix.sync.aligned.m8n8.x4.shared.b16 {%0,%1,%2,%3}, [%4];\n"
                 : "=r"(r[0]), "=r"(r[1]), "=r"(r[2]), "=r"(r[3]) : "r"(addr));
}
__device__ __forceinline__ void ldsm4t(uint32_t* r, uint32_t addr) {
    asm volatile("ldmatrix.sync.aligned.m8n8.x4.trans.shared.b16 {%0,%1,%2,%3}, [%4];\n"
                 : "=r"(r[0]), "=r"(r[1]), "=r"(r[2]), "=r"(r[3]) : "r"(addr));
}
__device__ __forceinline__ void mma_m16n8k16(float* c, const uint32_t* a, const uint32_t* b) {
    asm volatile(
        "mma.sync.aligned.m16n8k16.row.col.f32.f16.f16.f32 "
        "{%0,%1,%2,%3}, {%4,%5,%6,%7}, {%8,%9}, {%0,%1,%2,%3};\n"
        : "+f"(c[0]), "+f"(c[1]), "+f"(c[2]), "+f"(c[3])
        : "r"(a[0]), "r"(a[1]), "r"(a[2]), "r"(a[3]), "r"(b[0]), "r"(b[1]));
}
__device__ __forceinline__ float gelu_exact(float v) {
    return 0.5f * v * (1.0f + erff(v * 0.70710678118654752440f));
}

// ---------------------------------------------------------------------------
// Init / zero / convert
// ---------------------------------------------------------------------------
__global__ void init_kernel() {
    int t = threadIdx.x;
    if (t < NEXP) { g_cnt[t] = 0; g_imp[t] = 0.f; g_load[t] = 0; }
}

__global__ void zero_out_kernel(float* __restrict__ out, long n) {
    long i = (long)blockIdx.x * blockDim.x + threadIdx.x;
    long stride = (long)gridDim.x * blockDim.x;
    for (; i < n; i += stride) out[i] = 0.f;
}

__global__ void cvt_kernel(const float4* __restrict__ src, __half2* __restrict__ dst, long n4) {
    long i = (long)blockIdx.x * blockDim.x + threadIdx.x;
    if (i < n4) {
        float4 v = src[i];
        dst[2 * i]     = __floats2half2_rn(v.x, v.y);
        dst[2 * i + 1] = __floats2half2_rn(v.z, v.w);
    }
}

// ---------------------------------------------------------------------------
// Gating: one warp per token
// ---------------------------------------------------------------------------
__global__ void gating_kernel(const float* __restrict__ x,
                              const float* __restrict__ gw,
                              const float* __restrict__ gb) {
    __shared__ float s_imp[NEXP];
    __shared__ int   s_load[NEXP];
    int tid = threadIdx.x;
    if (tid < NEXP) { s_imp[tid] = 0.f; s_load[tid] = 0; }
    __syncthreads();

    int token = blockIdx.x * 8 + (tid >> 5);
    int lane  = tid & 31;

    float acc[NEXP];
#pragma unroll
    for (int e = 0; e < NEXP; e++) acc[e] = 0.f;

    const float* xr = x + (size_t)token * DDIM;
    for (int d = lane; d < DDIM; d += 32) {
        float xv = xr[d];
        const float4* gr = reinterpret_cast<const float4*>(gw + (size_t)d * NEXP);
        float4 g0 = gr[0], g1 = gr[1];
        acc[0] += xv * g0.x; acc[1] += xv * g0.y; acc[2] += xv * g0.z; acc[3] += xv * g0.w;
        acc[4] += xv * g1.x; acc[5] += xv * g1.y; acc[6] += xv * g1.z; acc[7] += xv * g1.w;
    }
#pragma unroll
    for (int e = 0; e < NEXP; e++) {
#pragma unroll
        for (int off = 16; off; off >>= 1)
            acc[e] += __shfl_xor_sync(0xffffffffu, acc[e], off);
    }

    if (lane == 0) {
        float l[NEXP];
        float mx = -1e30f;
#pragma unroll
        for (int e = 0; e < NEXP; e++) { l[e] = acc[e] + gb[e]; mx = fmaxf(mx, l[e]); }
        float p[NEXP], s = 0.f;
#pragma unroll
        for (int e = 0; e < NEXP; e++) { p[e] = expf(l[e] - mx); s += p[e]; }
        float inv = 1.f / s;
#pragma unroll
        for (int e = 0; e < NEXP; e++) atomicAdd(&s_imp[e], p[e] * inv);

        int i0 = 0;
#pragma unroll
        for (int e = 1; e < NEXP; e++) if (l[e] > l[i0]) i0 = e;
        int i1 = (i0 == 0) ? 1 : 0;
#pragma unroll
        for (int e = 0; e < NEXP; e++) if (e != i0 && l[e] > l[i1]) i1 = e;

        float w0 = 1.f / (1.f + expf(l[i1] - l[i0]));
        float w1 = 1.f - w0;

        int p0 = atomicAdd(&g_cnt[i0], 1);
        g_tok[i0 * NTOK + p0] = token; g_wt[i0 * NTOK + p0] = w0;
        int p1 = atomicAdd(&g_cnt[i1], 1);
        g_tok[i1 * NTOK + p1] = token; g_wt[i1 * NTOK + p1] = w1;
        atomicAdd(&s_load[i0], 1);
        atomicAdd(&s_load[i1], 1);
    }
    __syncthreads();
    if (tid < NEXP) {
        atomicAdd(&g_imp[tid], s_imp[tid]);
        atomicAdd(&g_load[tid], s_load[tid]);
    }
}

__global__ void prefix_kernel() {
    if (threadIdx.x == 0) {
        int s = 0;
#pragma unroll
        for (int e = 0; e < NEXP; e++) { g_base[e] = s; s += g_cnt[e]; }
        g_base[NEXP] = s;  // == 2*NTOK; shared expert rows follow
    }
}

__global__ void finalize_kernel(float* __restrict__ out, int out_size) {
    if (threadIdx.x == 0 && blockIdx.x == 0) {
        float si = 0.f, sl = 0.f, imp[NEXP], ld[NEXP];
#pragma unroll
        for (int e = 0; e < NEXP; e++) {
            imp[e] = g_imp[e]; ld[e] = (float)g_load[e];
            si += imp[e]; sl += ld[e];
        }
        float a = 0.f;
#pragma unroll
        for (int e = 0; e < NEXP; e++) {
            float d = imp[e] / (si + 1e-8f) - ld[e] / (sl + 1e-8f);
            a += d * d;
        }
        out[out_size - 1] = a;
    }
}

// ---------------------------------------------------------------------------
// Tiled fp16 mma GEMM. PHASE 1: h = gelu(gather(x) @ W1 + b1)  [K=1024, N=4096]
//                      PHASE 2: out += wt * (h @ W2 + b2)       [K=4096, N=1024]
// Block tile 128x128x32, 8 warps (4 x 2), double-buffered cp.async.
// grid.z = group (0..7 experts, 8 = shared expert).
// ---------------------------------------------------------------------------
template <int PHASE>
__global__ void __launch_bounds__(256, 2) moe_gemm(
    const float* __restrict__ bias_e,  // b1 [E,H] or b2 [E,D]
    const float* __restrict__ bias_s,  // sb1 or sb2
    float* __restrict__ out) {
    constexpr int KDIM = (PHASE == 1) ? DDIM : HDIM;
    constexpr int LDB  = (PHASE == 1) ? HDIM : DDIM;
    constexpr int KT   = KDIM / 32;

    const int g   = blockIdx.z;
    const int cnt = (g == NEXP) ? NTOK : g_cnt[g];
    const int m0  = blockIdx.y * 128;
    if (m0 >= cnt) return;
    const int n0   = blockIdx.x * 128;
    const int base = g_base[g];

    const __half* __restrict__ Bp =
        (PHASE == 1) ? ((g < NEXP) ? g_w1h + (size_t)g * DDIM * HDIM : g_sw1h)
                     : ((g < NEXP) ? g_w2h + (size_t)g * HDIM * DDIM : g_sw2h);
    const float* __restrict__ bias =
        (g < NEXP) ? bias_e + (size_t)g * ((PHASE == 1) ? HDIM : DDIM) : bias_s;

    // Padded strides: A rows 40 halfs (80 B), B rows 136 halfs (272 B) -> all
    // ldmatrix 16 B row fetches land on distinct banks (conflict-free).
    __shared__ __align__(16) __half As[2][128 * 40];
    __shared__ __align__(16) __half Bs[2][32 * 136];
    __shared__ int toks[128];

    const int tid = threadIdx.x;

    if (PHASE == 1) {
        if (tid < 128) {
            int m = m0 + tid;
            int t;
            if (g == NEXP) t = m;
            else           t = (m < cnt) ? g_tok[g * NTOK + m] : 0;
            toks[tid] = t;
        }
        __syncthreads();
    }

    // Per-thread global load descriptors (2 A-chunks + 2 B-chunks per stage)
    const int ar0 = tid >> 2;            // A row 0..63 (second chunk +64)
    const int ach = (tid & 3) * 8;       // A col chunk (halfs)
    const int br0 = tid >> 4;            // B row 0..15 (second chunk +16)
    const int bch = (tid & 15) * 8;      // B col chunk (halfs)

    const __half* arow0;
    const __half* arow1;
    if (PHASE == 1) {
        arow0 = g_xh + (size_t)toks[ar0] * DDIM;
        arow1 = g_xh + (size_t)toks[ar0 + 64] * DDIM;
    } else {
        arow0 = g_h + (size_t)(base + m0 + ar0) * HDIM;
        arow1 = g_h + (size_t)(base + m0 + ar0 + 64) * HDIM;
    }

    const uint32_t as0 = (uint32_t)__cvta_generic_to_shared(&As[0][0]);
    const uint32_t as1 = (uint32_t)__cvta_generic_to_shared(&As[1][0]);
    const uint32_t bs0 = (uint32_t)__cvta_generic_to_shared(&Bs[0][0]);
    const uint32_t bs1 = (uint32_t)__cvta_generic_to_shared(&Bs[1][0]);

    auto load_stage = [&](int kt, int buf) {
        const int k0 = kt * 32;
        uint32_t ab = buf ? as1 : as0;
        uint32_t bb = buf ? bs1 : bs0;
        cp_async16(ab + ((ar0)      * 40 + ach) * 2, arow0 + k0 + ach);
        cp_async16(ab + ((ar0 + 64) * 40 + ach) * 2, arow1 + k0 + ach);
        cp_async16(bb + ((br0)      * 136 + bch) * 2, Bp + (size_t)(k0 + br0)      * LDB + n0 + bch);
        cp_async16(bb + ((br0 + 16) * 136 + bch) * 2, Bp + (size_t)(k0 + br0 + 16) * LDB + n0 + bch);
        cp_commit();
    };

    const int lane = tid & 31;
    const int warp = tid >> 5;
    const int wm   = warp >> 1;  // 0..3  (32 rows each)
    const int wn   = warp & 1;   // 0..1  (64 cols each)

    float acc[2][8][4] = {};

    load_stage(0, 0);

    const int a_r = lane & 15;
    const int a_c = (lane >> 4) << 3;
    const int b_r = lane & 15;
    const int b_c = wn * 64 + ((lane >> 4) << 3);

    for (int kt = 0; kt < KT; kt++) {
        const int buf = kt & 1;
        if (kt + 1 < KT) { load_stage(kt + 1, buf ^ 1); cp_wait<1>(); }
        else             { cp_wait<0>(); }
        __syncthreads();

        const uint32_t ab = buf ? as1 : as0;
        const uint32_t bb = buf ? bs1 : bs0;

#pragma unroll
        for (int ks = 0; ks < 2; ks++) {
            uint32_t a[2][4], b[4][4];
#pragma unroll
            for (int mt = 0; mt < 2; mt++) {
                int r = wm * 32 + mt * 16 + a_r;
                int c = ks * 16 + a_c;
                ldsm4(a[mt], ab + (r * 40 + c) * 2);
            }
#pragma unroll
            for (int np = 0; np < 4; np++) {
                int r = ks * 16 + b_r;
                int c = b_c + np * 16;
                ldsm4t(b[np], bb + (r * 136 + c) * 2);
            }
#pragma unroll
            for (int mt = 0; mt < 2; mt++)
#pragma unroll
                for (int nt = 0; nt < 8; nt++)
                    mma_m16n8k16(acc[mt][nt], a[mt], &b[nt >> 1][(nt & 1) * 2]);
        }
        __syncthreads();
    }

    // Epilogue
    const int lr = lane >> 2;
    const int lc = (lane & 3) * 2;

    if (PHASE == 1) {
#pragma unroll
        for (int mt = 0; mt < 2; mt++) {
#pragma unroll
            for (int hh = 0; hh < 2; hh++) {
                int m = m0 + wm * 32 + mt * 16 + lr + hh * 8;
                if (m < cnt) {
                    __half* hp = g_h + (size_t)(base + m) * HDIM;
#pragma unroll
                    for (int nt = 0; nt < 8; nt++) {
                        int n = n0 + wn * 64 + nt * 8 + lc;
                        float v0 = gelu_exact(acc[mt][nt][hh * 2 + 0] + bias[n]);
                        float v1 = gelu_exact(acc[mt][nt][hh * 2 + 1] + bias[n + 1]);
                        *reinterpret_cast<__half2*>(hp + n) = __floats2half2_rn(v0, v1);
                    }
                }
            }
        }
    } else {
#pragma unroll
        for (int mt = 0; mt < 2; mt++) {
#pragma unroll
            for (int hh = 0; hh < 2; hh++) {
                int m = m0 + wm * 32 + mt * 16 + lr + hh * 8;
                if (m < cnt) {
                    int tok; float w;
                    if (g == NEXP) { tok = m; w = 1.0f; }
                    else           { tok = g_tok[g * NTOK + m]; w = g_wt[g * NTOK + m]; }
                    float* op = out + (size_t)tok * DDIM;
#pragma unroll
                    for (int nt = 0; nt < 8; nt++) {
                        int n = n0 + wn * 64 + nt * 8 + lc;
                        atomicAdd(op + n,     w * (acc[mt][nt][hh * 2 + 0] + bias[n]));
                        atomicAdd(op + n + 1, w * (acc[mt][nt][hh * 2 + 1] + bias[n + 1]));
                    }
                }
            }
        }
    }
}

// ---------------------------------------------------------------------------
// Launch
// ---------------------------------------------------------------------------
static void cvt_launch(const float* src, void* dst, size_t n) {
    size_t n4 = n / 4;
    int blocks = (int)((n4 + 255) / 256);
    cvt_kernel<<<blocks, 256>>>((const float4*)src, (__half2*)dst, (long)n4);
}

extern "C" void kernel_launch(void* const* d_in, const int* in_sizes, int n_in,
                              void* d_out, int out_size) {
    const float* x      = (const float*)d_in[0];
    const float* gate_w = (const float*)d_in[1];
    const float* gate_b = (const float*)d_in[2];
    const float* w1     = (const float*)d_in[3];
    const float* b1     = (const float*)d_in[4];
    const float* w2     = (const float*)d_in[5];
    const float* b2     = (const float*)d_in[6];
    const float* sw1    = (const float*)d_in[7];
    const float* sb1    = (const float*)d_in[8];
    const float* sw2    = (const float*)d_in[9];
    const float* sb2    = (const float*)d_in[10];
    float* out = (float*)d_out;

    void *p_xh, *p_w1h, *p_w2h, *p_sw1h, *p_sw2h;
    cudaGetSymbolAddress(&p_xh,   g_xh);
    cudaGetSymbolAddress(&p_w1h,  g_w1h);
    cudaGetSymbolAddress(&p_w2h,  g_w2h);
    cudaGetSymbolAddress(&p_sw1h, g_sw1h);
    cudaGetSymbolAddress(&p_sw2h, g_sw2h);

    init_kernel<<<1, 32>>>();
    zero_out_kernel<<<2048, 256>>>(out, (long)out_size);

    cvt_launch(x,   p_xh,   (size_t)NTOK * DDIM);
    cvt_launch(w1,  p_w1h,  (size_t)NEXP * DDIM * HDIM);
    cvt_launch(w2,  p_w2h,  (size_t)NEXP * HDIM * DDIM);
    cvt_launch(sw1, p_sw1h, (size_t)DDIM * HDIM);
    cvt_launch(sw2, p_sw2h, (size_t)HDIM * DDIM);

    gating_kernel<<<NTOK / 8, 256>>>(x, gate_w, gate_b);
    prefix_kernel<<<1, 32>>>();

    moe_gemm<1><<<dim3(HDIM / 128, NTOK / 128, NGRP), 256>>>(b1, sb1, out);
    moe_gemm<2><<<dim3(DDIM / 128, NTOK / 128, NGRP), 256>>>(b2, sb2, out);

    finalize_kernel<<<1, 32>>>(out, out_size);
}

// round 4
// speedup vs baseline: 1.0348x; 1.0348x over previous
#include <cuda_runtime.h>
#include <cuda_fp16.h>
#include <math.h>
#include <stdint.h>

#define NTOK 4096
#define DDIM 1024
#define HDIM 4096
#define NEXP 8
#define NGRP 9
#define SBASE (2 * NTOK)   // slot base of shared-expert rows (8192)
#define AROWS (3 * NTOK)   // 12288 compact rows total

// ---------------------------------------------------------------------------
// Device-global scratch
// ---------------------------------------------------------------------------
__device__ __half g_xa  [(size_t)AROWS * DDIM];             // gathered A (fp16)
__device__ __half g_w1h [(size_t)NEXP * DDIM * HDIM];       // w1 [E,D,H] fp16
__device__ __half g_w2h [(size_t)NEXP * HDIM * DDIM];       // w2 [E,H,D] fp16
__device__ __half g_sw1h[(size_t)DDIM * HDIM];
__device__ __half g_sw2h[(size_t)HDIM * DDIM];
__device__ __half g_h   [(size_t)AROWS * HDIM];             // hidden acts (fp16)
__device__ float  g_y   [(size_t)AROWS * DDIM];             // phase-2 out (pre-combine)
__device__ int    g_tok [NEXP * NTOK];
__device__ int    g_cnt [NEXP];
__device__ int    g_base[NGRP];
__device__ int    g_stok[SBASE];
__device__ int    g_te  [2 * NTOK];
__device__ int    g_tp  [2 * NTOK];
__device__ float  g_tw  [2 * NTOK];
__device__ float  g_imp [NEXP];
__device__ int    g_load[NEXP];

// ---------------------------------------------------------------------------
// PTX helpers
// ---------------------------------------------------------------------------
__device__ __forceinline__ void cp_async16(uint32_t s, const void* g) {
    asm volatile("cp.async.cg.shared.global [%0], [%1], 16;\n" :: "r"(s), "l"(g));
}
__device__ __forceinline__ void cp_commit() { asm volatile("cp.async.commit_group;\n"); }
template <int NN> __device__ __forceinline__ void cp_wait() {
    asm volatile("cp.async.wait_group %0;\n" :: "n"(NN));
}
__device__ __forceinline__ void ldsm4(uint32_t* r, uint32_t addr) {
    asm volatile("ldmatrix.sync.aligned.m8n8.x4.shared.b16 {%0,%1,%2,%3}, [%4];\n"
                 : "=r"(r[0]), "=r"(r[1]), "=r"(r[2]), "=r"(r[3]) : "r"(addr));
}
__device__ __forceinline__ void ldsm4t(uint32_t* r, uint32_t addr) {
    asm volatile("ldmatrix.sync.aligned.m8n8.x4.trans.shared.b16 {%0,%1,%2,%3}, [%4];\n"
                 : "=r"(r[0]), "=r"(r[1]), "=r"(r[2]), "=r"(r[3]) : "r"(addr));
}
__device__ __forceinline__ void mma_m16n8k16(float* c, const uint32_t* a, const uint32_t* b) {
    asm volatile(
        "mma.sync.aligned.m16n8k16.row.col.f32.f16.f16.f32 "
        "{%0,%1,%2,%3}, {%4,%5,%6,%7}, {%8,%9}, {%0,%1,%2,%3};\n"
        : "+f"(c[0]), "+f"(c[1]), "+f"(c[2]), "+f"(c[3])
        : "r"(a[0]), "r"(a[1]), "r"(a[2]), "r"(a[3]), "r"(b[0]), "r"(b[1]));
}
__device__ __forceinline__ float gelu_exact(float v) {
    return 0.5f * v * (1.0f + erff(v * 0.70710678118654752440f));
}

// ---------------------------------------------------------------------------
// Setup kernels
// ---------------------------------------------------------------------------
__global__ void init_kernel() {
    int t = threadIdx.x;
    if (t < NEXP) { g_cnt[t] = 0; g_imp[t] = 0.f; g_load[t] = 0; }
}

__global__ void cvt_kernel(const float4* __restrict__ src, __half2* __restrict__ dst, long n4) {
    long i = (long)blockIdx.x * blockDim.x + threadIdx.x;
    if (i < n4) {
        float4 v = src[i];
        dst[2 * i]     = __floats2half2_rn(v.x, v.y);
        dst[2 * i + 1] = __floats2half2_rn(v.z, v.w);
    }
}

// ---------------------------------------------------------------------------
// Gating: one warp per token
// ---------------------------------------------------------------------------
__global__ void gating_kernel(const float* __restrict__ x,
                              const float* __restrict__ gw,
                              const float* __restrict__ gb) {
    __shared__ float s_imp[NEXP];
    __shared__ int   s_load[NEXP];
    int tid = threadIdx.x;
    if (tid < NEXP) { s_imp[tid] = 0.f; s_load[tid] = 0; }
    __syncthreads();

    int token = blockIdx.x * 8 + (tid >> 5);
    int lane  = tid & 31;

    float acc[NEXP];
#pragma unroll
    for (int e = 0; e < NEXP; e++) acc[e] = 0.f;

    const float* xr = x + (size_t)token * DDIM;
    for (int d = lane; d < DDIM; d += 32) {
        float xv = xr[d];
        const float4* gr = reinterpret_cast<const float4*>(gw + (size_t)d * NEXP);
        float4 g0 = gr[0], g1 = gr[1];
        acc[0] += xv * g0.x; acc[1] += xv * g0.y; acc[2] += xv * g0.z; acc[3] += xv * g0.w;
        acc[4] += xv * g1.x; acc[5] += xv * g1.y; acc[6] += xv * g1.z; acc[7] += xv * g1.w;
    }
#pragma unroll
    for (int e = 0; e < NEXP; e++) {
#pragma unroll
        for (int off = 16; off; off >>= 1)
            acc[e] += __shfl_xor_sync(0xffffffffu, acc[e], off);
    }

    if (lane == 0) {
        float l[NEXP];
        float mx = -1e30f;
#pragma unroll
        for (int e = 0; e < NEXP; e++) { l[e] = acc[e] + gb[e]; mx = fmaxf(mx, l[e]); }
        float p[NEXP], s = 0.f;
#pragma unroll
        for (int e = 0; e < NEXP; e++) { p[e] = expf(l[e] - mx); s += p[e]; }
        float inv = 1.f / s;
#pragma unroll
        for (int e = 0; e < NEXP; e++) atomicAdd(&s_imp[e], p[e] * inv);

        int i0 = 0;
#pragma unroll
        for (int e = 1; e < NEXP; e++) if (l[e] > l[i0]) i0 = e;
        int i1 = (i0 == 0) ? 1 : 0;
#pragma unroll
        for (int e = 0; e < NEXP; e++) if (e != i0 && l[e] > l[i1]) i1 = e;

        float w0 = 1.f / (1.f + expf(l[i1] - l[i0]));
        float w1 = 1.f - w0;

        int p0 = atomicAdd(&g_cnt[i0], 1);
        g_tok[i0 * NTOK + p0] = token;
        g_te[2 * token] = i0; g_tp[2 * token] = p0; g_tw[2 * token] = w0;
        int p1 = atomicAdd(&g_cnt[i1], 1);
        g_tok[i1 * NTOK + p1] = token;
        g_te[2 * token + 1] = i1; g_tp[2 * token + 1] = p1; g_tw[2 * token + 1] = w1;
        atomicAdd(&s_load[i0], 1);
        atomicAdd(&s_load[i1], 1);
    }
    __syncthreads();
    if (tid < NEXP) {
        atomicAdd(&g_imp[tid], s_imp[tid]);
        atomicAdd(&g_load[tid], s_load[tid]);
    }
}

__global__ void prefix_kernel() {
    if (threadIdx.x == 0) {
        int s = 0;
#pragma unroll
        for (int e = 0; e < NEXP; e++) { g_base[e] = s; s += g_cnt[e]; }
        g_base[NEXP] = s;  // == SBASE
    }
}

__global__ void slotmap_kernel() {
    int e = blockIdx.x;
    int b = g_base[e], n = g_cnt[e];
    for (int i = threadIdx.x; i < n; i += blockDim.x)
        g_stok[b + i] = g_tok[e * NTOK + i];
}

// Build compact fp16 A: rows [0,8192) routed tokens, [8192,12288) identity
__global__ void gather_kernel(const float* __restrict__ x) {
    int r = blockIdx.x;
    int tok = (r < SBASE) ? g_stok[r] : (r - SBASE);
    const float4* src = reinterpret_cast<const float4*>(x + (size_t)tok * DDIM);
    uint4* dst = reinterpret_cast<uint4*>(g_xa + (size_t)r * DDIM);
    int t = threadIdx.x;  // 128 threads x 8 halfs
    float4 a = src[2 * t], b = src[2 * t + 1];
    __half2 h0 = __floats2half2_rn(a.x, a.y);
    __half2 h1 = __floats2half2_rn(a.z, a.w);
    __half2 h2 = __floats2half2_rn(b.x, b.y);
    __half2 h3 = __floats2half2_rn(b.z, b.w);
    uint4 o;
    o.x = *reinterpret_cast<uint32_t*>(&h0);
    o.y = *reinterpret_cast<uint32_t*>(&h1);
    o.z = *reinterpret_cast<uint32_t*>(&h2);
    o.w = *reinterpret_cast<uint32_t*>(&h3);
    dst[t] = o;
}

// ---------------------------------------------------------------------------
// Tiled fp16 mma GEMM, 128x128x32 tile, 8 warps, 4-stage cp.async ring.
// PHASE 1: g_h = gelu(g_xa @ w1[g] + b1)   (K=1024, N=4096)
// PHASE 2: g_y = g_h @ w2[g] + b2           (K=4096, N=1024)
// grid.z = group (0..7 experts, 8 = shared)
// ---------------------------------------------------------------------------
#define NSTAGE 4
#define A_STG (128 * 40)           // halfs per A stage (padded stride 40)
#define B_STG (32 * 136)           // halfs per B stage (padded stride 136)
#define SMEM_GEMM ((NSTAGE * (A_STG + B_STG)) * 2)  // 75776 bytes

template <int PHASE>
__global__ void __launch_bounds__(256, 2) moe_gemm(
    const float* __restrict__ bias_e,
    const float* __restrict__ bias_s) {
    constexpr int KDIM = (PHASE == 1) ? DDIM : HDIM;
    constexpr int LDB  = (PHASE == 1) ? HDIM : DDIM;
    constexpr int KT   = KDIM / 32;

    const int g   = blockIdx.z;
    const int cnt = (g == NEXP) ? NTOK : g_cnt[g];
    const int m0  = blockIdx.y * 128;
    if (m0 >= cnt) return;
    const int n0   = blockIdx.x * 128;
    const int base = g_base[g];

    const __half* __restrict__ Bp =
        (PHASE == 1) ? ((g < NEXP) ? g_w1h + (size_t)g * DDIM * HDIM : g_sw1h)
                     : ((g < NEXP) ? g_w2h + (size_t)g * HDIM * DDIM : g_sw2h);
    const float* __restrict__ bias =
        (g < NEXP) ? bias_e + (size_t)g * ((PHASE == 1) ? HDIM : DDIM) : bias_s;

    extern __shared__ __align__(16) __half smem[];
    __half* As = smem;                       // [NSTAGE][A_STG]
    __half* Bs = smem + NSTAGE * A_STG;      // [NSTAGE][B_STG]

    const int tid = threadIdx.x;

    // Global load mapping (round-1 verified): A 128x32, B 32x128 per stage
    const int ar0 = tid >> 2;            // A row 0..63 (+64 second chunk)
    const int ach = (tid & 3) * 8;       // A col chunk (halfs)
    const int br0 = tid >> 4;            // B row 0..15 (+16 second chunk)
    const int bch = (tid & 15) * 8;      // B col chunk (halfs)

    const __half* arow0 = ((PHASE == 1) ? g_xa : g_h) + (size_t)(base + m0 + ar0) * KDIM;
    const __half* arow1 = ((PHASE == 1) ? g_xa : g_h) + (size_t)(base + m0 + ar0 + 64) * KDIM;

    const uint32_t asb = (uint32_t)__cvta_generic_to_shared(As);
    const uint32_t bsb = (uint32_t)__cvta_generic_to_shared(Bs);

    auto load_stage = [&](int kt) {
        const int s = kt & (NSTAGE - 1);
        const int k0 = kt * 32;
        uint32_t ab = asb + s * (A_STG * 2);
        uint32_t bb = bsb + s * (B_STG * 2);
        cp_async16(ab + ((ar0)      * 40 + ach) * 2, arow0 + k0 + ach);
        cp_async16(ab + ((ar0 + 64) * 40 + ach) * 2, arow1 + k0 + ach);
        cp_async16(bb + ((br0)      * 136 + bch) * 2, Bp + (size_t)(k0 + br0)      * LDB + n0 + bch);
        cp_async16(bb + ((br0 + 16) * 136 + bch) * 2, Bp + (size_t)(k0 + br0 + 16) * LDB + n0 + bch);
        cp_commit();
    };

    load_stage(0); load_stage(1); load_stage(2);

    const int lane = tid & 31;
    const int warp = tid >> 5;
    const int wm   = warp >> 1;  // 0..3
    const int wn   = warp & 1;   // 0..1

    float acc[2][8][4] = {};

    const int a_r = lane & 15;
    const int a_c = (lane >> 4) << 3;
    const int b_r = lane & 15;
    const int b_c = wn * 64 + ((lane >> 4) << 3);

    for (int kt = 0; kt < KT; kt++) {
        // wait until stage kt is resident
        if (kt + 2 < KT)      cp_wait<2>();
        else if (kt + 1 < KT) cp_wait<1>();
        else                  cp_wait<0>();
        __syncthreads();  // all warps past compute(kt-1); stage kt visible to all

        if (kt + 3 < KT) load_stage(kt + 3);  // overwrites buf (kt-1)&3 — safe

        const int s = kt & (NSTAGE - 1);
        const uint32_t ab = asb + s * (A_STG * 2);
        const uint32_t bb = bsb + s * (B_STG * 2);

#pragma unroll
        for (int ks = 0; ks < 2; ks++) {
            uint32_t a[2][4], b[4][4];
#pragma unroll
            for (int mt = 0; mt < 2; mt++) {
                int r = wm * 32 + mt * 16 + a_r;
                int c = ks * 16 + a_c;
                ldsm4(a[mt], ab + (r * 40 + c) * 2);
            }
#pragma unroll
            for (int np = 0; np < 4; np++) {
                int r = ks * 16 + b_r;
                int c = b_c + np * 16;
                ldsm4t(b[np], bb + (r * 136 + c) * 2);
            }
#pragma unroll
            for (int mt = 0; mt < 2; mt++)
#pragma unroll
                for (int nt = 0; nt < 8; nt++)
                    mma_m16n8k16(acc[mt][nt], a[mt], &b[nt >> 1][(nt & 1) * 2]);
        }
    }

    // Epilogue (no atomics): phase1 -> g_h fp16 w/ gelu; phase2 -> g_y fp32
    const int lr = lane >> 2;
    const int lc = (lane & 3) * 2;

#pragma unroll
    for (int mt = 0; mt < 2; mt++) {
#pragma unroll
        for (int hh = 0; hh < 2; hh++) {
            int m = m0 + wm * 32 + mt * 16 + lr + hh * 8;
            if (m < cnt) {
                if (PHASE == 1) {
                    __half* hp = g_h + (size_t)(base + m) * HDIM;
#pragma unroll
                    for (int nt = 0; nt < 8; nt++) {
                        int n = n0 + wn * 64 + nt * 8 + lc;
                        float v0 = gelu_exact(acc[mt][nt][hh * 2 + 0] + bias[n]);
                        float v1 = gelu_exact(acc[mt][nt][hh * 2 + 1] + bias[n + 1]);
                        *reinterpret_cast<__half2*>(hp + n) = __floats2half2_rn(v0, v1);
                    }
                } else {
                    float* yp = g_y + (size_t)(base + m) * DDIM;
#pragma unroll
                    for (int nt = 0; nt < 8; nt++) {
                        int n = n0 + wn * 64 + nt * 8 + lc;
                        float2 v;
                        v.x = acc[mt][nt][hh * 2 + 0] + bias[n];
                        v.y = acc[mt][nt][hh * 2 + 1] + bias[n + 1];
                        *reinterpret_cast<float2*>(yp + n) = v;
                    }
                }
            }
        }
    }
}

// ---------------------------------------------------------------------------
// Combine: out[t] = w0*y[slot0] + w1*y[slot1] + y[shared slot]
// ---------------------------------------------------------------------------
__global__ void combine_kernel(float* __restrict__ out) {
    int t = blockIdx.x;
    int e0 = g_te[2 * t],   e1 = g_te[2 * t + 1];
    float w0 = g_tw[2 * t], w1 = g_tw[2 * t + 1];
    size_t s0 = (size_t)(g_base[e0] + g_tp[2 * t]);
    size_t s1 = (size_t)(g_base[e1] + g_tp[2 * t + 1]);
    const float4* y0 = reinterpret_cast<const float4*>(g_y + s0 * DDIM);
    const float4* y1 = reinterpret_cast<const float4*>(g_y + s1 * DDIM);
    const float4* ys = reinterpret_cast<const float4*>(g_y + (size_t)(SBASE + t) * DDIM);
    float4* op = reinterpret_cast<float4*>(out + (size_t)t * DDIM);
    int i = threadIdx.x;  // 256 threads x float4
    float4 a = y0[i], b = y1[i], c = ys[i];
    float4 o;
    o.x = w0 * a.x + w1 * b.x + c.x;
    o.y = w0 * a.y + w1 * b.y + c.y;
    o.z = w0 * a.z + w1 * b.z + c.z;
    o.w = w0 * a.w + w1 * b.w + c.w;
    op[i] = o;
}

__global__ void finalize_kernel(float* __restrict__ out, int out_size) {
    if (threadIdx.x == 0 && blockIdx.x == 0) {
        float si = 0.f, sl = 0.f, imp[NEXP], ld[NEXP];
#pragma unroll
        for (int e = 0; e < NEXP; e++) {
            imp[e] = g_imp[e]; ld[e] = (float)g_load[e];
            si += imp[e]; sl += ld[e];
        }
        float a = 0.f;
#pragma unroll
        for (int e = 0; e < NEXP; e++) {
            float d = imp[e] / (si + 1e-8f) - ld[e] / (sl + 1e-8f);
            a += d * d;
        }
        out[out_size - 1] = a;
    }
}

// ---------------------------------------------------------------------------
// Launch
// ---------------------------------------------------------------------------
static void cvt_launch(const float* src, void* dst, size_t n) {
    size_t n4 = n / 4;
    int blocks = (int)((n4 + 255) / 256);
    cvt_kernel<<<blocks, 256>>>((const float4*)src, (__half2*)dst, (long)n4);
}

extern "C" void kernel_launch(void* const* d_in, const int* in_sizes, int n_in,
                              void* d_out, int out_size) {
    const float* x      = (const float*)d_in[0];
    const float* gate_w = (const float*)d_in[1];
    const float* gate_b = (const float*)d_in[2];
    const float* w1     = (const float*)d_in[3];
    const float* b1     = (const float*)d_in[4];
    const float* w2     = (const float*)d_in[5];
    const float* b2     = (const float*)d_in[6];
    const float* sw1    = (const float*)d_in[7];
    const float* sb1    = (const float*)d_in[8];
    const float* sw2    = (const float*)d_in[9];
    const float* sb2    = (const float*)d_in[10];
    float* out = (float*)d_out;

    void *p_w1h, *p_w2h, *p_sw1h, *p_sw2h;
    cudaGetSymbolAddress(&p_w1h,  g_w1h);
    cudaGetSymbolAddress(&p_w2h,  g_w2h);
    cudaGetSymbolAddress(&p_sw1h, g_sw1h);
    cudaGetSymbolAddress(&p_sw2h, g_sw2h);

    cudaFuncSetAttribute(moe_gemm<1>, cudaFuncAttributeMaxDynamicSharedMemorySize, SMEM_GEMM);
    cudaFuncSetAttribute(moe_gemm<2>, cudaFuncAttributeMaxDynamicSharedMemorySize, SMEM_GEMM);

    init_kernel<<<1, 32>>>();

    cvt_launch(w1,  p_w1h,  (size_t)NEXP * DDIM * HDIM);
    cvt_launch(w2,  p_w2h,  (size_t)NEXP * HDIM * DDIM);
    cvt_launch(sw1, p_sw1h, (size_t)DDIM * HDIM);
    cvt_launch(sw2, p_sw2h, (size_t)HDIM * DDIM);

    gating_kernel<<<NTOK / 8, 256>>>(x, gate_w, gate_b);
    prefix_kernel<<<1, 32>>>();
    slotmap_kernel<<<NEXP, 256>>>();
    gather_kernel<<<AROWS, 128>>>(x);

    moe_gemm<1><<<dim3(HDIM / 128, NTOK / 128, NGRP), 256, SMEM_GEMM>>>(b1, sb1);
    moe_gemm<2><<<dim3(DDIM / 128, NTOK / 128, NGRP), 256, SMEM_GEMM>>>(b2, sb2);

    combine_kernel<<<NTOK, 256>>>(out);
    finalize_kernel<<<1, 32>>>(out, out_size);
}